// round 5
// baseline (speedup 1.0000x reference)
#include <cuda_runtime.h>
#include <cuda_fp16.h>
#include <cstdint>

// ============================================================================
// PWBLinearLayer: out[B,128] = x[B,1024] @ quantize(W)[1024,128] + quantize(b)
//
// Baseline-PTX tensor-core path (compute_100 — no tcgen05):
//   prep : Wq = round(clip(W,-1,1)*127) as EXACT integers in fp16, [k][n]
//   gemm : per-CTA M=128,N=128 tile; fully-async loads; NO full-CTA barrier
//          in the main loop — scoped named barriers instead:
//            * A rows are fetched+converted by the warp-pair that consumes
//              them  -> bar.sync(1+wm, 64)
//            * B halves (n 0-63 / 64-127) are fetched by the wn-group that
//              consumes them -> bar.sync(5+wn, 128)
//            * A32 fp32 staging is thread-local (cp.async wait only)
//          mma.sync m16n8k16 f16->f32 (hi-only: measured rel_err 2.1e-4);
//          epilogue scales 1/127 + quantized bias.
// ============================================================================

#define DINLINE __device__ __forceinline__

__device__ __align__(16) __half g_wh[1024 * 128];  // [k][n], n contiguous
__device__ float g_bq[128];

// ---------------------------------------------------------------------------
DINLINE uint32_t smem_u32(const void* p) {
    uint32_t a;
    asm("{ .reg .u64 t; cvta.to.shared.u64 t, %1; cvt.u32.u64 %0, t; }"
        : "=r"(a) : "l"(p));
    return a;
}

DINLINE void ldsm4(uint32_t (&r)[4], uint32_t addr) {
    asm volatile("ldmatrix.sync.aligned.m8n8.x4.shared.b16 {%0,%1,%2,%3}, [%4];"
                 : "=r"(r[0]), "=r"(r[1]), "=r"(r[2]), "=r"(r[3]) : "r"(addr));
}

DINLINE void ldsm4t(uint32_t (&r)[4], uint32_t addr) {
    asm volatile("ldmatrix.sync.aligned.m8n8.x4.trans.shared.b16 {%0,%1,%2,%3}, [%4];"
                 : "=r"(r[0]), "=r"(r[1]), "=r"(r[2]), "=r"(r[3]) : "r"(addr));
}

DINLINE void hmma(float (&d)[4], const uint32_t (&a)[4], const uint32_t (&b)[2]) {
    asm volatile(
        "mma.sync.aligned.m16n8k16.row.col.f32.f16.f16.f32 "
        "{%0,%1,%2,%3}, {%4,%5,%6,%7}, {%8,%9}, {%0,%1,%2,%3};"
        : "+f"(d[0]), "+f"(d[1]), "+f"(d[2]), "+f"(d[3])
        : "r"(a[0]), "r"(a[1]), "r"(a[2]), "r"(a[3]), "r"(b[0]), "r"(b[1]));
}

DINLINE void cp_async16(uint32_t saddr, const void* gaddr) {
    asm volatile("cp.async.cg.shared.global [%0], [%1], 16;"
                 :: "r"(saddr), "l"(gaddr));
}
#define CP_COMMIT()  asm volatile("cp.async.commit_group;" ::: "memory")
#define CP_WAIT(n)   asm volatile("cp.async.wait_group %0;" :: "n"(n) : "memory")
#define BAR_SYNC(id, cnt) \
    asm volatile("bar.sync %0, %1;" :: "r"(id), "r"(cnt) : "memory")

DINLINE uint32_t cvt2(float v0, float v1) {
    __half2 h = __floats2half2_rn(v0, v1);
    return *reinterpret_cast<uint32_t*>(&h);
}

// ---------------------------------------------------------------------------
// Prep: quantize W (exact ints in fp16, [k][n]); quantize bias.
// ---------------------------------------------------------------------------
__global__ void pwb_prep_kernel(const float* __restrict__ W,
                                const float* __restrict__ b) {
    int idx = blockIdx.x * blockDim.x + threadIdx.x;
    if (idx < 1024 * 128) {
        float w = W[idx];
        w = fminf(fmaxf(w, -1.0f), 1.0f);
        g_wh[idx] = __float2half_rn(rintf(w * 127.0f));  // int in [-127,127]
    }
    if (idx < 128) {
        float v = fminf(fmaxf(b[idx], -1.0f), 1.0f);
        g_bq[idx] = rintf(v * 127.0f) * (1.0f / 127.0f);
    }
}

// ---------------------------------------------------------------------------
// GEMM kernel. SMEM map (102400 B total):
//   A32 ring : 3 stages x 16384 B. 128 rows x 128 B fp32; 16-B chunk c
//              (0..7) at row r stored at phys chunk c ^ (r&7).  Thread-local.
//   B16 ring : 4 stages x 8192 B. 32 k-rows x 256 B; chunk c (0..15)
//              at row k -> (c&8) | ((c^k)&7).  wn-half fetched by wn-group.
//   A16 bufs : 2 x 10240 B. 128 rows x 80 B pitch (64 B fp16 data);
//              chunk c (0..3) at c*16 — 80-B pitch keeps ldmatrix
//              conflict-free without XOR.
// ---------------------------------------------------------------------------
static constexpr int STAGE_A32 = 16384;
static constexpr int NSTAGE_A  = 3;
static constexpr int STAGE_B   = 8192;
static constexpr int NSTAGE_B  = 4;
static constexpr int STAGE_A16 = 10240;
static constexpr int OFF_A32   = 0;
static constexpr int OFF_B     = NSTAGE_A * STAGE_A32;            // 49152
static constexpr int OFF_A16   = OFF_B + NSTAGE_B * STAGE_B;      // 81920
static constexpr int SMEM_TOTAL = OFF_A16 + 2 * STAGE_A16;        // 102400
static constexpr int THREADS  = 256;
static constexpr int KCHUNKS  = 32;   // 1024 / 32

__global__ __launch_bounds__(THREADS, 2)
void pwb_gemm_kernel(const float* __restrict__ x, float* __restrict__ out) {
    extern __shared__ char smem[];
    const uint32_t sb = smem_u32(smem);
    const int tid  = threadIdx.x;
    const int wid  = tid >> 5;
    const int lane = tid & 31;
    const int wm   = wid >> 1;   // 0..3  (M pair)
    const int wn   = wid & 1;    // 0..1  (N half)
    const int tile = blockIdx.x;

    const float* xg = x + (size_t)tile * 128 * 1024;

    // pair-local thread id (0..63): owns half a row of the pair's 32 M-rows
    const int q    = wn * 32 + lane;
    const int arow = wm * 32 + (q >> 1);
    const int ah   = q & 1;
    // group-local thread id (0..127) within the wn-group {warps wn,wn+2,..}
    const int gq   = wm * 32 + lane;

    // ---- async A fetch: thread fetches exactly what it later converts ----
    auto ldA = [&](int stage, int kc) {
        uint32_t dst = sb + OFF_A32 + stage * STAGE_A32 + arow * 128;
        const float* src = xg + (size_t)arow * 1024 + kc * 32 + ah * 16;
        #pragma unroll
        for (int i = 0; i < 4; ++i) {
            uint32_t c = (uint32_t)(ah * 4 + i);
            uint32_t phys = c ^ (arow & 7);
            cp_async16(dst + phys * 16, src + i * 4);
        }
    };
    // ---- async B fetch: wn-group fetches ONLY its n-half (4 KB/chunk) ----
    auto ldB = [&](int stage, int kc) {
        #pragma unroll
        for (int t = 0; t < 2; ++t) {
            int i   = gq * 2 + t;           // 0..255
            int row = i >> 3;               // 0..31
            int c   = wn * 8 + (i & 7);     // this group's chunk half
            uint32_t phys = (uint32_t)((c & 8) | ((c ^ row) & 7));
            cp_async16(sb + OFF_B + stage * STAGE_B + row * 256 + phys * 16,
                       g_wh + (size_t)(kc * 32 + row) * 128 + c * 8);
        }
    };
    // ---- smem fp32 -> fp16 convert (thread-local round trip) ----
    auto convertA = [&](int srcStage, int dstBuf) {
        uint32_t sA = sb + OFF_A32 + srcStage * STAGE_A32 + arow * 128;
        float4 v[4];
        #pragma unroll
        for (int i = 0; i < 4; ++i) {
            uint32_t c = (uint32_t)(ah * 4 + i);
            uint32_t phys = c ^ (arow & 7);
            asm volatile("ld.shared.v4.f32 {%0,%1,%2,%3}, [%4];"
                         : "=f"(v[i].x), "=f"(v[i].y), "=f"(v[i].z), "=f"(v[i].w)
                         : "r"(sA + phys * 16));
        }
        uint32_t h[8];
        #pragma unroll
        for (int i = 0; i < 4; ++i) {
            h[2 * i]     = cvt2(v[i].x, v[i].y);
            h[2 * i + 1] = cvt2(v[i].z, v[i].w);
        }
        uint32_t dA = sb + OFF_A16 + dstBuf * STAGE_A16 + arow * 80 + ah * 32;
        asm volatile("st.shared.v4.b32 [%0], {%1,%2,%3,%4};"
                     :: "r"(dA), "r"(h[0]), "r"(h[1]), "r"(h[2]), "r"(h[3]) : "memory");
        asm volatile("st.shared.v4.b32 [%0], {%1,%2,%3,%4};"
                     :: "r"(dA + 16), "r"(h[4]), "r"(h[5]), "r"(h[6]), "r"(h[7]) : "memory");
    };

    // ---- accumulators ----
    float acc[2][8][4];
    #pragma unroll
    for (int mt = 0; mt < 2; ++mt)
        #pragma unroll
        for (int nt = 0; nt < 8; ++nt)
            #pragma unroll
            for (int i = 0; i < 4; ++i) acc[mt][nt][i] = 0.0f;

    const int lr = lane & 15;
    const int lc = lane >> 4;

    auto compute = [&](int a16buf, int bstage) {
        uint32_t aBase = sb + OFF_A16 + a16buf * STAGE_A16;
        uint32_t bBase = sb + OFF_B + bstage * STAGE_B;
        #pragma unroll
        for (int kt = 0; kt < 2; ++kt) {
            uint32_t bfr[8][2];
            #pragma unroll
            for (int j = 0; j < 4; ++j) {
                int row = kt * 16 + lr;
                int cn  = wn * 8 + j * 2 + lc;
                uint32_t phys = (uint32_t)((cn & 8) | ((cn ^ row) & 7));
                uint32_t r[4];
                ldsm4t(r, bBase + row * 256 + phys * 16);
                bfr[2 * j][0] = r[0]; bfr[2 * j][1] = r[1];
                bfr[2 * j + 1][0] = r[2]; bfr[2 * j + 1][1] = r[3];
            }
            #pragma unroll
            for (int mt = 0; mt < 2; ++mt) {
                int row = wm * 32 + mt * 16 + lr;
                uint32_t ch = (uint32_t)(kt * 2 + lc);     // 0..3, no XOR
                uint32_t a[4];
                ldsm4(a, aBase + row * 80 + ch * 16);
                #pragma unroll
                for (int nt = 0; nt < 8; ++nt) hmma(acc[mt][nt], a, bfr[nt]);
            }
        }
    };

    // ---- prologue: chunks 0 and 1 in flight ----
    ldA(0, 0); ldB(0, 0); CP_COMMIT();
    ldA(1, 1); ldB(1, 1); CP_COMMIT();

    // ---- main loop: no full-CTA barrier ----
    const int barA = 1 + wm;   // 64-thread pair barrier
    const int barB = 5 + wn;   // 128-thread group barrier
    for (int kc = 0; kc < KCHUNKS; ++kc) {
        if (kc + 2 < KCHUNKS) {
            ldA((kc + 2) % NSTAGE_A, kc + 2);
            ldB((kc + 2) % NSTAGE_B, kc + 2);
            CP_COMMIT();
        }
        if (kc < KCHUNKS - 2)       { CP_WAIT(2); }
        else if (kc == KCHUNKS - 2) { CP_WAIT(1); }
        else                        { CP_WAIT(0); }
        BAR_SYNC(barB, 128);            // B half for chunk kc visible to group
        convertA(kc % NSTAGE_A, kc & 1);
        BAR_SYNC(barA, 64);             // pair's A16 rows visible
        compute(kc & 1, kc % NSTAGE_B);
    }

    // ---- epilogue: scale + bias (g_bq via L2), direct STG ----
    const float s = 1.0f / 127.0f;
    float* og = out + (size_t)tile * 128 * 128;
    const int col0 = wn * 64 + (lane & 3) * 2;
    #pragma unroll
    for (int mt = 0; mt < 2; ++mt) {
        int r0 = wm * 32 + mt * 16 + (lane >> 2);
        #pragma unroll
        for (int nt = 0; nt < 8; ++nt) {
            int col = col0 + nt * 8;
            float b0 = g_bq[col], b1 = g_bq[col + 1];
            float2 v0 = make_float2(acc[mt][nt][0] * s + b0,
                                    acc[mt][nt][1] * s + b1);
            float2 v1 = make_float2(acc[mt][nt][2] * s + b0,
                                    acc[mt][nt][3] * s + b1);
            *reinterpret_cast<float2*>(og + (size_t)r0 * 128 + col) = v0;
            *reinterpret_cast<float2*>(og + (size_t)(r0 + 8) * 128 + col) = v1;
        }
    }
}

// ---------------------------------------------------------------------------
extern "C" void kernel_launch(void* const* d_in, const int* in_sizes, int n_in,
                              void* d_out, int out_size) {
    const float* x = (const float*)d_in[0];   // [B, 1024]
    const float* W = (const float*)d_in[1];   // [1024, 128]
    const float* b = (const float*)d_in[2];   // [128]
    float* out = (float*)d_out;               // [B, 128]

    const int Mrows = in_sizes[0] / 1024;
    const int grid  = Mrows / 128;

    cudaFuncSetAttribute(pwb_gemm_kernel,
                         cudaFuncAttributeMaxDynamicSharedMemorySize,
                         SMEM_TOTAL);

    pwb_prep_kernel<<<(1024 * 128 + 255) / 256, 256>>>(W, b);
    pwb_gemm_kernel<<<grid, THREADS, SMEM_TOTAL>>>(x, out);
}

// round 6
// speedup vs baseline: 1.2938x; 1.2938x over previous
#include <cuda_runtime.h>
#include <cuda_fp16.h>
#include <cuda.h>
#include <cstdint>

// ============================================================================
// PWBLinearLayer: out[B,128] = x[B,1024] @ quantize(W)[1024,128] + quantize(b)
//
// Baseline-PTX path at compute_100 (no tcgen05; TMA + mbarrier ARE sm_90
// baseline PTX and legal here):
//   prep : Wq = round(clip(W,-1,1)*127) as EXACT integers in fp16, [k][n]
//   gemm : per-CTA M=128,N=128 tile.
//          A (fp32 x) : 2D TMA ring (3 stages) -> smem fp32 -> cvt fp16 smem
//          B (fp16 Wq): 2D TMA ring (4 stages), two SW128 half-tiles
//          mma.sync m16n8k16 f16->f32 (hi-only, measured rel_err 2.1e-4);
//          epilogue scales 1/127 + quantized bias.
//   Rationale: R4/R5 ncu shows the L1/LSU wavefront pipe is the binding
//   resource; TMA moves all global->smem traffic onto the idle TMA engine.
// ============================================================================

#define DINLINE __device__ __forceinline__

__device__ __align__(128) __half g_wh[1024 * 128];  // [k][n], n contiguous
__device__ float g_bq[128];

// ---------------------------------------------------------------------------
DINLINE uint32_t smem_u32(const void* p) {
    uint32_t a;
    asm("{ .reg .u64 t; cvta.to.shared.u64 t, %1; cvt.u32.u64 %0, t; }"
        : "=r"(a) : "l"(p));
    return a;
}

DINLINE void ldsm4(uint32_t (&r)[4], uint32_t addr) {
    asm volatile("ldmatrix.sync.aligned.m8n8.x4.shared.b16 {%0,%1,%2,%3}, [%4];"
                 : "=r"(r[0]), "=r"(r[1]), "=r"(r[2]), "=r"(r[3]) : "r"(addr));
}

DINLINE void ldsm4t(uint32_t (&r)[4], uint32_t addr) {
    asm volatile("ldmatrix.sync.aligned.m8n8.x4.trans.shared.b16 {%0,%1,%2,%3}, [%4];"
                 : "=r"(r[0]), "=r"(r[1]), "=r"(r[2]), "=r"(r[3]) : "r"(addr));
}

DINLINE void hmma(float (&d)[4], const uint32_t (&a)[4], const uint32_t (&b)[2]) {
    asm volatile(
        "mma.sync.aligned.m16n8k16.row.col.f32.f16.f16.f32 "
        "{%0,%1,%2,%3}, {%4,%5,%6,%7}, {%8,%9}, {%0,%1,%2,%3};"
        : "+f"(d[0]), "+f"(d[1]), "+f"(d[2]), "+f"(d[3])
        : "r"(a[0]), "r"(a[1]), "r"(a[2]), "r"(a[3]), "r"(b[0]), "r"(b[1]));
}

DINLINE uint32_t cvt2(float v0, float v1) {
    __half2 h = __floats2half2_rn(v0, v1);
    return *reinterpret_cast<uint32_t*>(&h);
}

#define MBAR_INIT(a, c)                                                        \
    asm volatile("mbarrier.init.shared.b64 [%0], %1;"                          \
                 :: "r"(a), "r"(c) : "memory")
#define MBAR_EXPECT_TX(a, bytes)                                               \
    asm volatile("mbarrier.arrive.expect_tx.shared.b64 _, [%0], %1;"           \
                 :: "r"(a), "r"(bytes) : "memory")

DINLINE void mbar_wait(uint32_t addr, uint32_t parity) {
    asm volatile(
        "{\n\t.reg .pred P;\n\t"
        "WAIT_%=:\n\t"
        "mbarrier.try_wait.parity.shared.b64 P, [%0], %1;\n\t"
        "@P bra.uni DONE_%=;\n\t"
        "bra.uni WAIT_%=;\n\t"
        "DONE_%=:\n\t}"
        :: "r"(addr), "r"(parity) : "memory");
}

#define TMA2D(dst, tmap, cx, cy, mbar)                                         \
    asm volatile(                                                              \
        "cp.async.bulk.tensor.2d.shared::cta.global.tile"                      \
        ".mbarrier::complete_tx::bytes [%0], [%1, {%2, %3}], [%4];"            \
        :: "r"(dst), "l"(tmap), "r"(cx), "r"(cy), "r"(mbar) : "memory")

// ---------------------------------------------------------------------------
// Prep: quantize W (exact ints in fp16, [k][n]); quantize bias.
// ---------------------------------------------------------------------------
__global__ void pwb_prep_kernel(const float* __restrict__ W,
                                const float* __restrict__ b) {
    int idx = blockIdx.x * blockDim.x + threadIdx.x;
    if (idx < 1024 * 128) {
        float w = W[idx];
        w = fminf(fmaxf(w, -1.0f), 1.0f);
        g_wh[idx] = __float2half_rn(rintf(w * 127.0f));  // int in [-127,127]
    }
    if (idx < 128) {
        float v = fminf(fmaxf(b[idx], -1.0f), 1.0f);
        g_bq[idx] = rintf(v * 127.0f) * (1.0f / 127.0f);
    }
}

// ---------------------------------------------------------------------------
// GEMM kernel. SMEM map (102464 B):
//   A32 ring : 3 x 16384 B. 128 rows x 128 B fp32, TMA SW128
//              (16-B chunk c at row r -> phys chunk c ^ (r&7)).
//   B16 ring : 4 x 8192 B. Two SW128 half-tiles per stage:
//              half h (n = h*64..h*64+63) at +h*4096; 32 k-rows x 128 B.
//   A16 bufs : 2 x 10240 B. 128 rows x 80 B pitch (ldmatrix conflict-free).
//   mbars    : at 102400; mbarA[3], mbarB[4].
// ---------------------------------------------------------------------------
static constexpr int STAGE_A32 = 16384;
static constexpr int NSTAGE_A  = 3;
static constexpr int STAGE_B   = 8192;
static constexpr int NSTAGE_B  = 4;
static constexpr int STAGE_A16 = 10240;
static constexpr int OFF_A32   = 0;
static constexpr int OFF_B     = NSTAGE_A * STAGE_A32;            // 49152
static constexpr int OFF_A16   = OFF_B + NSTAGE_B * STAGE_B;      // 81920
static constexpr int OFF_MBAR  = OFF_A16 + 2 * STAGE_A16;         // 102400
static constexpr int OFF_MBARB = OFF_MBAR + 32;
static constexpr int SMEM_TOTAL = OFF_MBAR + 64;                  // 102464
static constexpr int THREADS  = 256;
static constexpr int KCHUNKS  = 32;   // 1024 / 32

__global__ __launch_bounds__(THREADS, 2)
void pwb_gemm_kernel(const __grid_constant__ CUtensorMap tmA,
                     const __grid_constant__ CUtensorMap tmB,
                     float* __restrict__ out) {
    extern __shared__ char smem[];
    const uint32_t sb = smem_u32(smem);
    const int tid  = threadIdx.x;
    const int wid  = tid >> 5;
    const int lane = tid & 31;
    const int wm   = wid >> 1;   // 0..3  (M)
    const int wn   = wid & 1;    // 0..1  (N)
    const int tile = blockIdx.x;

    if (tid == 0) {
        #pragma unroll
        for (int s = 0; s < NSTAGE_A; ++s) MBAR_INIT(sb + OFF_MBAR + s * 8, 1);
        #pragma unroll
        for (int s = 0; s < NSTAGE_B; ++s) MBAR_INIT(sb + OFF_MBARB + s * 8, 1);
    }
    __syncthreads();

    // single-thread TMA issue for chunk kc
    auto issue = [&](int kc) {
        uint32_t mA = sb + OFF_MBAR + (kc % NSTAGE_A) * 8;
        uint32_t mB = sb + OFF_MBARB + (kc % NSTAGE_B) * 8;
        uint32_t dA = sb + OFF_A32 + (kc % NSTAGE_A) * STAGE_A32;
        uint32_t dB = sb + OFF_B + (kc % NSTAGE_B) * STAGE_B;
        MBAR_EXPECT_TX(mA, STAGE_A32);
        TMA2D(dA, &tmA, kc * 32, tile * 128, mA);
        MBAR_EXPECT_TX(mB, STAGE_B);
        TMA2D(dB, &tmB, 0, kc * 32, mB);
        TMA2D(dB + 4096, &tmB, 64, kc * 32, mB);
    };

    const int arow = tid >> 1;          // 0..127
    const int ah   = tid & 1;           // which 16-k half of the 32-k chunk

    // ---- smem fp32 -> fp16 convert (thread-local round trip) ----
    auto convertA = [&](int srcStage, int dstBuf) {
        uint32_t sA = sb + OFF_A32 + srcStage * STAGE_A32 + arow * 128;
        float4 v[4];
        #pragma unroll
        for (int i = 0; i < 4; ++i) {
            uint32_t c = (uint32_t)(ah * 4 + i);
            uint32_t phys = c ^ (arow & 7);
            asm volatile("ld.shared.v4.f32 {%0,%1,%2,%3}, [%4];"
                         : "=f"(v[i].x), "=f"(v[i].y), "=f"(v[i].z), "=f"(v[i].w)
                         : "r"(sA + phys * 16));
        }
        uint32_t h[8];
        #pragma unroll
        for (int i = 0; i < 4; ++i) {
            h[2 * i]     = cvt2(v[i].x, v[i].y);
            h[2 * i + 1] = cvt2(v[i].z, v[i].w);
        }
        uint32_t dA = sb + OFF_A16 + dstBuf * STAGE_A16 + arow * 80 + ah * 32;
        asm volatile("st.shared.v4.b32 [%0], {%1,%2,%3,%4};"
                     :: "r"(dA), "r"(h[0]), "r"(h[1]), "r"(h[2]), "r"(h[3]) : "memory");
        asm volatile("st.shared.v4.b32 [%0], {%1,%2,%3,%4};"
                     :: "r"(dA + 16), "r"(h[4]), "r"(h[5]), "r"(h[6]), "r"(h[7]) : "memory");
    };

    // ---- accumulators ----
    float acc[2][8][4];
    #pragma unroll
    for (int mt = 0; mt < 2; ++mt)
        #pragma unroll
        for (int nt = 0; nt < 8; ++nt)
            #pragma unroll
            for (int i = 0; i < 4; ++i) acc[mt][nt][i] = 0.0f;

    const int lr = lane & 15;
    const int lc = lane >> 4;

    auto compute = [&](int a16buf, int bstage) {
        uint32_t aBase = sb + OFF_A16 + a16buf * STAGE_A16;
        uint32_t bBase = sb + OFF_B + bstage * STAGE_B;
        #pragma unroll
        for (int kt = 0; kt < 2; ++kt) {
            uint32_t bfr[8][2];
            #pragma unroll
            for (int j = 0; j < 4; ++j) {
                int row = kt * 16 + lr;
                int cn  = wn * 8 + j * 2 + lc;
                uint32_t addr = bBase + ((uint32_t)(cn & 8) << 9)   // half sel
                              + row * 128 + (((cn ^ row) & 7) << 4);
                uint32_t r[4];
                ldsm4t(r, addr);
                bfr[2 * j][0] = r[0]; bfr[2 * j][1] = r[1];
                bfr[2 * j + 1][0] = r[2]; bfr[2 * j + 1][1] = r[3];
            }
            #pragma unroll
            for (int mt = 0; mt < 2; ++mt) {
                int row = wm * 32 + mt * 16 + lr;
                uint32_t ch = (uint32_t)(kt * 2 + lc);     // 0..3, no XOR
                uint32_t a[4];
                ldsm4(a, aBase + row * 80 + ch * 16);
                #pragma unroll
                for (int nt = 0; nt < 8; ++nt) hmma(acc[mt][nt], a, bfr[nt]);
            }
        }
    };

    // ---- prologue: chunks 0 and 1 in flight ----
    if (tid == 0) { issue(0); issue(1); }

    // ---- main loop: 1 __syncthreads per chunk ----
    for (int kc = 0; kc < KCHUNKS; ++kc) {
        if (tid == 0 && kc + 2 < KCHUNKS) issue(kc + 2);
        mbar_wait(sb + OFF_MBAR  + (kc % NSTAGE_A) * 8, (kc / NSTAGE_A) & 1);
        mbar_wait(sb + OFF_MBARB + (kc % NSTAGE_B) * 8, (kc / NSTAGE_B) & 1);
        convertA(kc % NSTAGE_A, kc & 1);
        __syncthreads();
        compute(kc & 1, kc % NSTAGE_B);
    }

    // ---- epilogue: scale + bias (g_bq via L2), direct STG ----
    const float s = 1.0f / 127.0f;
    float* og = out + (size_t)tile * 128 * 128;
    const int col0 = wn * 64 + (lane & 3) * 2;
    #pragma unroll
    for (int mt = 0; mt < 2; ++mt) {
        int r0 = wm * 32 + mt * 16 + (lane >> 2);
        #pragma unroll
        for (int nt = 0; nt < 8; ++nt) {
            int col = col0 + nt * 8;
            float b0 = g_bq[col], b1 = g_bq[col + 1];
            float2 v0 = make_float2(acc[mt][nt][0] * s + b0,
                                    acc[mt][nt][1] * s + b1);
            float2 v1 = make_float2(acc[mt][nt][2] * s + b0,
                                    acc[mt][nt][3] * s + b1);
            *reinterpret_cast<float2*>(og + (size_t)r0 * 128 + col) = v0;
            *reinterpret_cast<float2*>(og + (size_t)(r0 + 8) * 128 + col) = v1;
        }
    }
}

// ---------------------------------------------------------------------------
// Host: build tensormaps via driver entry point (no -lcuda link dependency).
// All host work happens at graph-capture time — free during timed replays.
// ---------------------------------------------------------------------------
typedef CUresult (*EncodeTiledFn)(
    CUtensorMap*, CUtensorMapDataType, cuuint32_t, void*,
    const cuuint64_t*, const cuuint64_t*, const cuuint32_t*, const cuuint32_t*,
    CUtensorMapInterleave, CUtensorMapSwizzle, CUtensorMapL2promotion,
    CUtensorMapFloatOOBfill);

extern "C" void kernel_launch(void* const* d_in, const int* in_sizes, int n_in,
                              void* d_out, int out_size) {
    const float* x = (const float*)d_in[0];   // [B, 1024]
    const float* W = (const float*)d_in[1];   // [1024, 128]
    const float* b = (const float*)d_in[2];   // [128]
    float* out = (float*)d_out;               // [B, 128]

    const int Mrows = in_sizes[0] / 1024;
    const int grid  = Mrows / 128;

    void* fn = nullptr;
    cudaDriverEntryPointQueryResult qres;
    cudaGetDriverEntryPoint("cuTensorMapEncodeTiled", &fn,
                            cudaEnableDefault, &qres);
    EncodeTiledFn encode = (EncodeTiledFn)fn;

    void* whp = nullptr;
    cudaGetSymbolAddress(&whp, g_wh);

    // A: x [Mrows, 1024] fp32; box 32 cols x 128 rows, SW128 (32*4=128B)
    CUtensorMap tmA;
    {
        cuuint64_t dims[2]    = {1024, (cuuint64_t)Mrows};
        cuuint64_t strides[1] = {1024 * sizeof(float)};
        cuuint32_t box[2]     = {32, 128};
        cuuint32_t estr[2]    = {1, 1};
        encode(&tmA, CU_TENSOR_MAP_DATA_TYPE_FLOAT32, 2, (void*)x,
               dims, strides, box, estr,
               CU_TENSOR_MAP_INTERLEAVE_NONE, CU_TENSOR_MAP_SWIZZLE_128B,
               CU_TENSOR_MAP_L2_PROMOTION_L2_128B,
               CU_TENSOR_MAP_FLOAT_OOB_FILL_NONE);
    }
    // B: g_wh [1024, 128] fp16; box 64 cols x 32 rows, SW128 (64*2=128B)
    CUtensorMap tmB;
    {
        cuuint64_t dims[2]    = {128, 1024};
        cuuint64_t strides[1] = {128 * sizeof(__half)};
        cuuint32_t box[2]     = {64, 32};
        cuuint32_t estr[2]    = {1, 1};
        encode(&tmB, CU_TENSOR_MAP_DATA_TYPE_FLOAT16, 2, whp,
               dims, strides, box, estr,
               CU_TENSOR_MAP_INTERLEAVE_NONE, CU_TENSOR_MAP_SWIZZLE_128B,
               CU_TENSOR_MAP_L2_PROMOTION_L2_128B,
               CU_TENSOR_MAP_FLOAT_OOB_FILL_NONE);
    }

    cudaFuncSetAttribute(pwb_gemm_kernel,
                         cudaFuncAttributeMaxDynamicSharedMemorySize,
                         SMEM_TOTAL);

    pwb_prep_kernel<<<(1024 * 128 + 255) / 256, 256>>>(W, b);
    pwb_gemm_kernel<<<grid, THREADS, SMEM_TOTAL>>>(tmA, tmB, out);
}